// round 2
// baseline (speedup 1.0000x reference)
#include <cuda_runtime.h>

// SparseEmbedding: out[b, :] = sum_n vals[b,n] * kernel[idx[b,n], :] + bias
// BATCH=4096, NNZ=32, VOCAB=1e6, DIM=64. float32 everywhere, idx int32.
//
// R1 strategy: one warp per batch row, but each gather step services TWO nnz
// rows at once: lanes 0-15 load 16B (float4) of row idx[n], lanes 16-31 load
// row idx[n+1]. 16 LDG.128 per warp instead of 32 LDG.64 -> half the issue
// slots, more loads in flight. Final shfl_xor(16) merges the two halves.

#define BATCH 4096
#define NNZ   32
#define DIM   64

__global__ void __launch_bounds__(128) sparse_embedding_kernel(
    const int*   __restrict__ idx,
    const float* __restrict__ vals,
    const float* __restrict__ table,
    const float* __restrict__ bias,
    float*       __restrict__ out)
{
    const int gwarp = (blockIdx.x * blockDim.x + threadIdx.x) >> 5;
    const int lane  = threadIdx.x & 31;
    if (gwarp >= BATCH) return;

    const int half = lane >> 4;   // 0: even nnz, 1: odd nnz
    const int sub  = lane & 15;   // dim group: owns dims [4*sub, 4*sub+4)

    // Each lane holds one (idx, val) pair for this row; broadcast via shfl.
    const int   my_idx = idx[gwarp * NNZ + lane];
    const float my_val = vals[gwarp * NNZ + lane];

    float4 acc = make_float4(0.0f, 0.0f, 0.0f, 0.0f);

#pragma unroll
    for (int n = 0; n < NNZ; n += 2) {
        const int   id = __shfl_sync(0xffffffffu, my_idx, n + half);
        const float v  = __shfl_sync(0xffffffffu, my_val, n + half);
        const float4 kv = __ldg(reinterpret_cast<const float4*>(
            table + (size_t)id * DIM) + sub);
        acc.x = fmaf(v, kv.x, acc.x);
        acc.y = fmaf(v, kv.y, acc.y);
        acc.z = fmaf(v, kv.z, acc.z);
        acc.w = fmaf(v, kv.w, acc.w);
    }

    // Merge the two nnz halves: lane l and lane l^16 hold the same dims.
    acc.x += __shfl_xor_sync(0xffffffffu, acc.x, 16);
    acc.y += __shfl_xor_sync(0xffffffffu, acc.y, 16);
    acc.z += __shfl_xor_sync(0xffffffffu, acc.z, 16);
    acc.w += __shfl_xor_sync(0xffffffffu, acc.w, 16);

    if (half == 0) {
        const float4 b = reinterpret_cast<const float4*>(bias)[sub];
        acc.x += b.x;
        acc.y += b.y;
        acc.z += b.z;
        acc.w += b.w;
        reinterpret_cast<float4*>(out + (size_t)gwarp * DIM)[sub] = acc;
    }
}

extern "C" void kernel_launch(void* const* d_in, const int* in_sizes, int n_in,
                              void* d_out, int out_size)
{
    const int*   idx   = (const int*)  d_in[0];
    const float* vals  = (const float*)d_in[1];
    const float* table = (const float*)d_in[2];
    const float* bias  = (const float*)d_in[3];
    float*       out   = (float*)d_out;

    // 4096 warps total, 4 warps (128 threads) per block -> 1024 blocks.
    const int threads = 128;
    const int blocks  = (BATCH * 32) / threads;
    sparse_embedding_kernel<<<blocks, threads>>>(idx, vals, table, bias, out);
}

// round 3
// speedup vs baseline: 1.0332x; 1.0332x over previous
#include <cuda_runtime.h>

// SparseEmbedding: out[b, :] = sum_n vals[b,n] * kernel[idx[b,n], :] + bias
// BATCH=4096, NNZ=32, VOCAB=1e6, DIM=64. float32 everywhere, idx int32.
//
// R2 strategy: one warp per batch row, lane l owns dims [2l, 2l+1] (float2).
// Key change vs R0/R1: explicitly PREFETCH all 32 gathered rows into a
// register array (kv[32] = 64 regs) before accumulating, and allow a large
// register budget (__launch_bounds__(128, 1)). This forces MLP=32 per warp
// so the ~600-cycle DRAM gather latency is fully overlapped; the kernel
// should then run at the LTS/DRAM bandwidth floor (~32MB compulsory traffic).

#define BATCH 4096
#define NNZ   32
#define DIM   64

__global__ void __launch_bounds__(128, 1) sparse_embedding_kernel(
    const int*   __restrict__ idx,
    const float* __restrict__ vals,
    const float* __restrict__ table,
    const float* __restrict__ bias,
    float*       __restrict__ out)
{
    const int gwarp = (blockIdx.x * blockDim.x + threadIdx.x) >> 5;
    const int lane  = threadIdx.x & 31;
    if (gwarp >= BATCH) return;

    // Each lane holds one (idx, val) pair for this row; broadcast via shfl.
    const int   my_idx = idx[gwarp * NNZ + lane];
    const float my_val = vals[gwarp * NNZ + lane];

    // Phase 1: issue ALL 32 gather loads (independent -> 32 in flight).
    float2 kv[NNZ];
#pragma unroll
    for (int n = 0; n < NNZ; ++n) {
        const int id = __shfl_sync(0xffffffffu, my_idx, n);
        kv[n] = __ldg(reinterpret_cast<const float2*>(
            table + (size_t)id * DIM) + lane);
    }

    // Phase 2: accumulate.
    float2 acc = reinterpret_cast<const float2*>(bias)[lane];
#pragma unroll
    for (int n = 0; n < NNZ; ++n) {
        const float v = __shfl_sync(0xffffffffu, my_val, n);
        acc.x = fmaf(v, kv[n].x, acc.x);
        acc.y = fmaf(v, kv[n].y, acc.y);
    }

    reinterpret_cast<float2*>(out + (size_t)gwarp * DIM)[lane] = acc;
}

extern "C" void kernel_launch(void* const* d_in, const int* in_sizes, int n_in,
                              void* d_out, int out_size)
{
    const int*   idx   = (const int*)  d_in[0];
    const float* vals  = (const float*)d_in[1];
    const float* table = (const float*)d_in[2];
    const float* bias  = (const float*)d_in[3];
    float*       out   = (float*)d_out;

    // 4096 warps total, 4 warps (128 threads) per block -> 1024 blocks.
    const int threads = 128;
    const int blocks  = (BATCH * 32) / threads;
    sparse_embedding_kernel<<<blocks, threads>>>(idx, vals, table, bias, out);
}